// round 5
// baseline (speedup 1.0000x reference)
#include <cuda_runtime.h>
#include <math.h>

#define B    64
#define T    2048
#define D    128
#define H    256
#define G4   1024
#define OUTN 64
#define MROWS (T * B)          // 131072
#define NB_L0 128              // layer-0 blocks (2 j each)
#define NB_L1 256              // layer-1 blocks (1 j each)
#define NBLK  (NB_L0 + NB_L1)  // 384
#define RING 8

typedef unsigned long long ull;

// ---------------- scratch ----------------------------------------------------
__device__ float g_e[(size_t)MROWS * D];           // [m][d]
__device__ float g_xg0[(size_t)MROWS * G4];        // [t][col][b]
__device__ float g_h1all[(size_t)MROWS * H];       // [t][j][b]
__device__ float g_logits[(size_t)MROWS * OUTN];   // [m][o]
__device__ float g_h0buf[RING][H * B];             // [ring][k][b]
__device__ float g_h1buf[RING][H * B];
__device__ float g_bias0[G4];
__device__ int   g_done0q[T][4];                   // warp-arrival counters (128 each)
__device__ int   g_done1q[T][4];

// ---------------- packed f32x2 helpers ---------------------------------------
#define FMA2(d, a, b) asm("fma.rn.f32x2 %0, %1, %2, %0;" : "+l"(d) : "l"(a), "l"(b))
#define ADD2(d, a, b) asm("add.rn.f32x2 %0, %1, %2;"     : "=l"(d) : "l"(a), "l"(b))
__device__ __forceinline__ ull dup2(float w) {
    ull d; unsigned u = __float_as_uint(w);
    asm("mov.b64 %0, {%1, %1};" : "=l"(d) : "r"(u));
    return d;
}

__device__ __forceinline__ float sigf(float x) { return 1.f / (1.f + __expf(-x)); }
__device__ __forceinline__ float tanh_f(float x) {
    float e = __expf(-2.f * fabsf(x));
    float r = (1.f - e) / (1.f + e);
    return copysignf(r, x);
}

__device__ __forceinline__ void waitq(const int* p, int thr) {
    int v;
    do {
        asm volatile("ld.global.acquire.gpu.b32 %0, [%1];" : "=r"(v) : "l"(p) : "memory");
    } while (v < thr);
}

__device__ __forceinline__ void arrive_rel(int* p) {
    asm volatile("red.release.gpu.global.add.u32 [%0], %1;" :: "l"(p), "r"(1) : "memory");
}

// ---------------- tiny kernels ------------------------------------------------
__global__ void prep_bias(const float* __restrict__ bih0, const float* __restrict__ bhh0) {
    int i = blockIdx.x * 256 + threadIdx.x;
    if (i < G4) g_bias0[i] = bih0[i] + bhh0[i];
}

__global__ void embed_kernel(const int* __restrict__ x, const float* __restrict__ table) {
    size_t idx = (size_t)blockIdx.x * 256 + threadIdx.x;    // over MROWS*D
    int d = (int)(idx & (D - 1));
    size_t m = idx >> 7;                                    // m = t*64 + b
    int t = (int)(m >> 6);
    int b = (int)(m & 63);
    int xi = __ldg(&x[(size_t)b * T + t]);
    g_e[idx] = (xi == 0) ? 0.f : __ldg(&table[(size_t)xi * D + d]);
}

// ------- xg0[t][col][b] = (e @ Wih0^T)[m][col] + bias0[col] ; K=128 ----------
__global__ void __launch_bounds__(256, 2) gemm_xg0(const float* __restrict__ Wih) {
    __shared__ float As[32][132];
    __shared__ float Bs[32][132];
    const int tid = threadIdx.x;
    const int tx = tid & 15, ty = tid >> 4;    // tx -> m dir, ty -> n dir
    const size_t m0 = (size_t)blockIdx.y * 128;
    const int    n0 = blockIdx.x * 128;

    ull acc[4][8];   // [m-pair][n]
#pragma unroll
    for (int p = 0; p < 4; p++)
#pragma unroll
        for (int j = 0; j < 8; j++) acc[p][j] = 0ULL;

    for (int kc = 0; kc < D; kc += 32) {
        for (int i = tid; i < 128 * 32; i += 256) {
            int mm = i >> 5, k = i & 31;
            As[k][mm] = g_e[(m0 + mm) * D + kc + k];
        }
        for (int i = tid; i < 128 * 32; i += 256) {
            int nn = i >> 5, k = i & 31;
            Bs[k][nn] = Wih[(size_t)(n0 + nn) * D + kc + k];
        }
        __syncthreads();
#pragma unroll
        for (int k = 0; k < 32; k++) {
            ulonglong2 a01 = *(const ulonglong2*)&As[k][tx * 8];
            ulonglong2 a23 = *(const ulonglong2*)&As[k][tx * 8 + 4];
            float4 f0 = *(const float4*)&Bs[k][ty * 8];
            float4 f1 = *(const float4*)&Bs[k][ty * 8 + 4];
            ull bb[8];
            bb[0] = dup2(f0.x); bb[1] = dup2(f0.y); bb[2] = dup2(f0.z); bb[3] = dup2(f0.w);
            bb[4] = dup2(f1.x); bb[5] = dup2(f1.y); bb[6] = dup2(f1.z); bb[7] = dup2(f1.w);
#pragma unroll
            for (int j = 0; j < 8; j++) {
                FMA2(acc[0][j], a01.x, bb[j]);
                FMA2(acc[1][j], a01.y, bb[j]);
                FMA2(acc[2][j], a23.x, bb[j]);
                FMA2(acc[3][j], a23.y, bb[j]);
            }
        }
        __syncthreads();
    }
    const int tq = (int)(m0 >> 6) + (tx >> 3);
    const int bb0 = (tx & 7) * 8;
#pragma unroll
    for (int j = 0; j < 8; j++) {
        int col = n0 + ty * 8 + j;
        ull bd = dup2(g_bias0[col]);
        ull v0, v1, v2, v3;
        ADD2(v0, acc[0][j], bd); ADD2(v1, acc[1][j], bd);
        ADD2(v2, acc[2][j], bd); ADD2(v3, acc[3][j], bd);
        float* dst = g_xg0 + ((size_t)tq * G4 + col) * B + bb0;
        ulonglong2 q0; q0.x = v0; q0.y = v1;
        ulonglong2 q1; q1.x = v2; q1.y = v3;
        *(ulonglong2*)dst       = q0;
        *(ulonglong2*)(dst + 4) = q1;
    }
}

// ---------------- persistent pipelined 2-layer LSTM --------------------------
__global__ void __launch_bounds__(128, 3) lstm_kernel(
    const float* __restrict__ Whh0,
    const float* __restrict__ Wih1,
    const float* __restrict__ Whh1,
    const float* __restrict__ bih1,
    const float* __restrict__ bhh1)
{
    __shared__ ull   w_s2[2048];      // weights pre-duplicated (w,w)
    __shared__ float red[2][2048];    // k-split partials, step-parity buffered
    const int bid = blockIdx.x, tid = threadIdx.x;
    const int lane = tid & 31;

    if (bid < NB_L0) {
        // ========== layer 0 : 2 j's -> 8 rows (r = g*2+jl), K=256 ===========
        const int j0 = bid * 2, q0 = bid >> 5;
        for (int i = tid; i < 2048; i += 128) {
            int r = i >> 8, k = i & 255;
            float w = Whh0[(size_t)((r >> 1) * 256 + j0 + (r & 1)) * H + k];
            w_s2[i] = dup2(w);
        }
        const int bg = tid & 15, cg = (tid >> 4) & 1, ks = tid >> 5;  // warp = ks
        const int b0 = bg * 4, kbase = ks * 64, rbase = cg * 4;
        const int ab = tid & 63, jl = tid >> 6;
        float c_reg = 0.f;
        __syncthreads();

        for (int t = 0; t < T; ++t) {
            // prefetch xg0 (DRAM) before any waiting
            const float* xgp = g_xg0 + ((size_t)t * G4 + j0 + jl) * B + ab;
            float xp0 = xgp[0];
            float xp1 = xgp[(size_t)256 * B];
            float xp2 = xgp[(size_t)512 * B];
            float xp3 = xgp[(size_t)768 * B];

            if (lane == 0) {
                if (t >= 1)    waitq(&g_done0q[t - 1][ks], 128);
                if (t >= RING) waitq(&g_done1q[t - RING][ks], 128);
            }
            __syncwarp();

            const float* hb = g_h0buf[(t + RING - 1) & (RING - 1)] + b0;
            float* redp = red[t & 1];
            ull acc0[4], acc1[4];
#pragma unroll
            for (int c = 0; c < 4; c++) { acc0[c] = 0ULL; acc1[c] = 0ULL; }

            ulonglong2 hv[2][4];
#pragma unroll
            for (int kc = 0; kc < 4; kc++)
                hv[0][kc] = *(const ulonglong2*)(hb + (size_t)(kbase + kc) * B);
#pragma unroll
            for (int it = 0; it < 16; ++it) {
                const int cur = it & 1, nxt = cur ^ 1;
                if (it < 15) {
#pragma unroll
                    for (int kc = 0; kc < 4; kc++)
                        hv[nxt][kc] = *(const ulonglong2*)(hb + (size_t)(kbase + (it + 1) * 4 + kc) * B);
                }
                const ull* wb = w_s2 + kbase + it * 4;
#pragma unroll
                for (int cc = 0; cc < 4; cc++) {
                    const ull* wr = wb + (rbase + cc) * 256;
                    ulonglong2 w01 = *(const ulonglong2*)(wr);
                    ulonglong2 w23 = *(const ulonglong2*)(wr + 2);
                    FMA2(acc0[cc], hv[cur][0].x, w01.x); FMA2(acc1[cc], hv[cur][0].y, w01.x);
                    FMA2(acc0[cc], hv[cur][1].x, w01.y); FMA2(acc1[cc], hv[cur][1].y, w01.y);
                    FMA2(acc0[cc], hv[cur][2].x, w23.x); FMA2(acc1[cc], hv[cur][2].y, w23.x);
                    FMA2(acc0[cc], hv[cur][3].x, w23.y); FMA2(acc1[cc], hv[cur][3].y, w23.y);
                }
            }
#pragma unroll
            for (int cc = 0; cc < 4; cc++) {
                ulonglong2 v; v.x = acc0[cc]; v.y = acc1[cc];
                *(ulonglong2*)&redp[ks * 512 + (rbase + cc) * 64 + b0] = v;
            }
            __syncthreads();   // red ready; also: all warps' waits passed -> safe to write h

            {   // activation: one (b, jl) pair per thread
                int r0 = (0 * 2 + jl) * 64 + ab, r1 = (1 * 2 + jl) * 64 + ab;
                int r2 = (2 * 2 + jl) * 64 + ab, r3 = (3 * 2 + jl) * 64 + ab;
                float s0 = xp0 + redp[r0] + redp[512 + r0] + redp[1024 + r0] + redp[1536 + r0];
                float s1 = xp1 + redp[r1] + redp[512 + r1] + redp[1024 + r1] + redp[1536 + r1];
                float s2 = xp2 + redp[r2] + redp[512 + r2] + redp[1024 + r2] + redp[1536 + r2];
                float s3 = xp3 + redp[r3] + redp[512 + r3] + redp[1024 + r3] + redp[1536 + r3];
                c_reg = sigf(s1) * c_reg + sigf(s0) * tanh_f(s2);
                float hval = sigf(s3) * tanh_f(c_reg);
                g_h0buf[t & (RING - 1)][(j0 + jl) * B + ab] = hval;
            }
            __syncwarp();
            if (lane == 0) arrive_rel(&g_done0q[t][q0]);
        }
    } else {
        // ========== layer 1 : 1 j -> 4 rows (r = g), K=512 ===================
        const int j = bid - NB_L0, q1 = j >> 6;
        for (int i = tid; i < 2048; i += 128) {
            int r = i >> 9, k = i & 511;
            float w = (k < 256) ? Wih1[(size_t)(r * 256 + j) * H + k]
                                : Whh1[(size_t)(r * 256 + j) * H + (k - 256)];
            w_s2[i] = dup2(w);
        }
        const int bg = tid & 15, ks = tid >> 4;   // ks in [0,8); warp w covers ks {2w,2w+1}
        const int b0 = bg * 4;
        const int wql = (ks & 6);                 // first quarter index of this warp's pair
        float bi0 = 0.f, bi1 = 0.f, bi2 = 0.f, bi3 = 0.f;
        if (tid < 64) {
            bi0 = bih1[0 * 256 + j] + bhh1[0 * 256 + j];
            bi1 = bih1[1 * 256 + j] + bhh1[1 * 256 + j];
            bi2 = bih1[2 * 256 + j] + bhh1[2 * 256 + j];
            bi3 = bih1[3 * 256 + j] + bhh1[3 * 256 + j];
        }
        float c_reg = 0.f;
        __syncthreads();

        for (int tp = 0; tp < T; ++tp) {
            if (lane == 0) {
                if (ks < 4) {
                    waitq(&g_done0q[tp][wql],     128);
                    waitq(&g_done0q[tp][wql + 1], 128);
                } else if (tp >= 1) {
                    waitq(&g_done1q[tp - 1][wql - 4], 128);
                    waitq(&g_done1q[tp - 1][wql - 3], 128);
                }
            }
            __syncwarp();

            const float* hb = ((ks < 4) ? g_h0buf[tp & (RING - 1)]
                                        : g_h1buf[(tp + RING - 1) & (RING - 1)]) + b0;
            float* redp = red[tp & 1];
            const int kloc = (ks & 3) * 64;
            ull acc0[4], acc1[4];
#pragma unroll
            for (int c = 0; c < 4; c++) { acc0[c] = 0ULL; acc1[c] = 0ULL; }

            ulonglong2 hv[2][4];
#pragma unroll
            for (int kc = 0; kc < 4; kc++)
                hv[0][kc] = *(const ulonglong2*)(hb + (size_t)(kloc + kc) * B);
#pragma unroll
            for (int it = 0; it < 16; ++it) {
                const int cur = it & 1, nxt = cur ^ 1;
                if (it < 15) {
#pragma unroll
                    for (int kc = 0; kc < 4; kc++)
                        hv[nxt][kc] = *(const ulonglong2*)(hb + (size_t)(kloc + (it + 1) * 4 + kc) * B);
                }
                const ull* wb = w_s2 + ks * 64 + it * 4;
#pragma unroll
                for (int cc = 0; cc < 4; cc++) {
                    const ull* wr = wb + cc * 512;
                    ulonglong2 w01 = *(const ulonglong2*)(wr);
                    ulonglong2 w23 = *(const ulonglong2*)(wr + 2);
                    FMA2(acc0[cc], hv[cur][0].x, w01.x); FMA2(acc1[cc], hv[cur][0].y, w01.x);
                    FMA2(acc0[cc], hv[cur][1].x, w01.y); FMA2(acc1[cc], hv[cur][1].y, w01.y);
                    FMA2(acc0[cc], hv[cur][2].x, w23.x); FMA2(acc1[cc], hv[cur][2].y, w23.x);
                    FMA2(acc0[cc], hv[cur][3].x, w23.y); FMA2(acc1[cc], hv[cur][3].y, w23.y);
                }
            }
#pragma unroll
            for (int cc = 0; cc < 4; cc++) {
                ulonglong2 v; v.x = acc0[cc]; v.y = acc1[cc];
                *(ulonglong2*)&redp[ks * 256 + cc * 64 + b0] = v;
            }
            __syncthreads();   // red ready; all warps' waits passed -> safe to write h

            if (tid < 64) {
                int b = tid;
                float s0 = bi0, s1 = bi1, s2 = bi2, s3 = bi3;
#pragma unroll
                for (int q = 0; q < 8; q++) {
                    const float* rp = redp + q * 256 + b;
                    s0 += rp[0]; s1 += rp[64]; s2 += rp[128]; s3 += rp[192];
                }
                c_reg = sigf(s1) * c_reg + sigf(s0) * tanh_f(s2);
                float hval = sigf(s3) * tanh_f(c_reg);
                g_h1buf[tp & (RING - 1)][j * B + b] = hval;
                g_h1all[((size_t)tp * H + j) * B + b] = hval;
                __syncwarp();
                if (lane == 0) arrive_rel(&g_done1q[tp][q1]);
            }
        }
    }
}

// ------- FC: logits[m][o] = h1[m] . fcW[o] + fcb ; A = g_h1all[t][k][b] ------
__global__ void __launch_bounds__(256) gemm_fc(const float* __restrict__ fcW,
                                               const float* __restrict__ fcb) {
    __shared__ float As[32][132];
    __shared__ float Bs[32][68];
    const int tid = threadIdx.x;
    const int tx = tid & 15, ty = tid >> 4;
    const size_t m0 = (size_t)blockIdx.x * 128;
    const int t0 = (int)(m0 >> 6);

    float acc[8][4];
#pragma unroll
    for (int i = 0; i < 8; i++)
#pragma unroll
        for (int j = 0; j < 4; j++) acc[i][j] = 0.f;

    for (int kc = 0; kc < H; kc += 32) {
        for (int i = tid; i < 32 * 128; i += 256) {
            int k = i >> 7, mm = i & 127;
            int tq = t0 + (mm >> 6), b = mm & 63;
            As[k][mm] = g_h1all[(size_t)tq * (H * B) + (size_t)(kc + k) * B + b];
        }
        for (int i = tid; i < 64 * 32; i += 256) {
            int nn = i >> 5, k = i & 31;
            Bs[k][nn] = fcW[(size_t)nn * H + kc + k];
        }
        __syncthreads();
#pragma unroll
        for (int k = 0; k < 32; k++) {
            float a[8], bb[4];
#pragma unroll
            for (int i = 0; i < 8; i++) a[i] = As[k][ty * 8 + i];
#pragma unroll
            for (int j = 0; j < 4; j++) bb[j] = Bs[k][tx * 4 + j];
#pragma unroll
            for (int i = 0; i < 8; i++)
#pragma unroll
                for (int j = 0; j < 4; j++) acc[i][j] += a[i] * bb[j];
        }
        __syncthreads();
    }
#pragma unroll
    for (int i = 0; i < 8; i++) {
        size_t row = (m0 + ty * 8 + i) * OUTN + tx * 4;
#pragma unroll
        for (int j = 0; j < 4; j++)
            g_logits[row + j] = acc[i][j] + fcb[tx * 4 + j];
    }
}

// ---------------- softmax over 64, remap [t][b] -> out[b][t] -----------------
__global__ void softmax_kernel(float* __restrict__ out) {
    const int tid = threadIdx.x;
    const int lane = tid & 31, w = tid >> 5;
    size_t row = (size_t)blockIdx.x * 8 + w;   // row = t*64 + b
    const float* L = g_logits + row * OUTN;
    float v0 = L[lane], v1 = L[lane + 32];
    float mx = fmaxf(v0, v1);
#pragma unroll
    for (int off = 16; off; off >>= 1) mx = fmaxf(mx, __shfl_xor_sync(~0u, mx, off));
    float e0 = expf(v0 - mx), e1 = expf(v1 - mx);
    float s = e0 + e1;
#pragma unroll
    for (int off = 16; off; off >>= 1) s += __shfl_xor_sync(~0u, s, off);
    float inv = 1.f / s;
    int t = (int)(row >> 6), b = (int)(row & 63);
    float* O = out + ((size_t)b * T + t) * OUTN;
    O[lane]      = e0 * inv;
    O[lane + 32] = e1 * inv;
}

// ---------------- launch ------------------------------------------------------
extern "C" void kernel_launch(void* const* d_in, const int* in_sizes, int n_in,
                              void* d_out, int out_size) {
    const int*   x     = (const int*)d_in[0];
    const float* table = (const float*)d_in[1];
    const float* Wih0  = (const float*)d_in[2];
    const float* Whh0  = (const float*)d_in[3];
    const float* bih0  = (const float*)d_in[4];
    const float* bhh0  = (const float*)d_in[5];
    const float* Wih1  = (const float*)d_in[6];
    const float* Whh1  = (const float*)d_in[7];
    const float* bih1  = (const float*)d_in[8];
    const float* bhh1  = (const float*)d_in[9];
    const float* fcW   = (const float*)d_in[10];
    const float* fcb   = (const float*)d_in[11];
    float* out = (float*)d_out;

    // reset counters + zero-state ring buffers every launch (graph-capturable)
    void *p0, *p1, *ph0, *ph1;
    cudaGetSymbolAddress(&p0,  g_done0q);
    cudaGetSymbolAddress(&p1,  g_done1q);
    cudaGetSymbolAddress(&ph0, g_h0buf);
    cudaGetSymbolAddress(&ph1, g_h1buf);
    cudaMemsetAsync(p0,  0, T * 4 * sizeof(int));
    cudaMemsetAsync(p1,  0, T * 4 * sizeof(int));
    cudaMemsetAsync(ph0, 0, RING * H * B * sizeof(float));
    cudaMemsetAsync(ph1, 0, RING * H * B * sizeof(float));

    prep_bias<<<4, 256>>>(bih0, bhh0);
    embed_kernel<<<(MROWS * D) / 256, 256>>>(x, table);
    gemm_xg0<<<dim3(8, MROWS / 128), 256>>>(Wih0);

    lstm_kernel<<<NBLK, 128>>>(Whh0, Wih1, Whh1, bih1, bhh1);

    gemm_fc<<<MROWS / 128, 256>>>(fcW, fcb);
    softmax_kernel<<<MROWS / 8, 256>>>(out);
}

// round 6
// speedup vs baseline: 1.4391x; 1.4391x over previous
#include <cuda_runtime.h>
#include <math.h>

#define B    64
#define T    2048
#define D    128
#define H    256
#define G4   1024
#define OUTN 64
#define MROWS (T * B)          // 131072
#define NB_L0 64               // layer-0 blocks (4 j each)
#define NB_L1 128              // layer-1 blocks (2 j each)
#define NBLK  (NB_L0 + NB_L1)  // 192
#define RING 4

typedef unsigned long long ull;

// ---------------- scratch ----------------------------------------------------
__device__ float g_e[(size_t)MROWS * D];           // [m][d]
__device__ float g_xg0[(size_t)MROWS * G4];        // [t][col][b]
__device__ float g_h1all[(size_t)MROWS * H];       // [t][j][b]
__device__ float g_logits[(size_t)MROWS * OUTN];   // [m][o]
__device__ float g_h0buf[RING][H * B];             // [ring][k][b]
__device__ float g_h1buf[RING][H * B];
__device__ float g_bias0[G4];
__device__ int   g_done0q[T][4];                   // block arrivals (16 per quarter)
__device__ int   g_done1q[T][4];                   // block arrivals (32 per quarter)

// ---------------- packed f32x2 helpers ---------------------------------------
#define FMA2(d, a, b) asm("fma.rn.f32x2 %0, %1, %2, %0;" : "+l"(d) : "l"(a), "l"(b))
#define ADD2(d, a, b) asm("add.rn.f32x2 %0, %1, %2;"     : "=l"(d) : "l"(a), "l"(b))
__device__ __forceinline__ ull dup2(float w) {
    ull d; unsigned u = __float_as_uint(w);
    asm("mov.b64 %0, {%1, %1};" : "=l"(d) : "r"(u));
    return d;
}

__device__ __forceinline__ float sigf(float x) { return 1.f / (1.f + __expf(-x)); }
__device__ __forceinline__ float tanh_f(float x) {
    float e = __expf(-2.f * fabsf(x));
    float r = (1.f - e) / (1.f + e);
    return copysignf(r, x);
}

__device__ __forceinline__ void waitq(const int* p, int thr) {
    int v;
    do {
        asm volatile("ld.global.acquire.gpu.b32 %0, [%1];" : "=r"(v) : "l"(p) : "memory");
    } while (v < thr);
}

__device__ __forceinline__ void arrive_rel(int* p) {
    asm volatile("red.release.gpu.global.add.u32 [%0], %1;" :: "l"(p), "r"(1) : "memory");
}

// ---------------- tiny kernels ------------------------------------------------
__global__ void prep_bias(const float* __restrict__ bih0, const float* __restrict__ bhh0) {
    int i = blockIdx.x * 256 + threadIdx.x;
    if (i < G4) g_bias0[i] = bih0[i] + bhh0[i];
}

__global__ void embed_kernel(const int* __restrict__ x, const float* __restrict__ table) {
    size_t idx = (size_t)blockIdx.x * 256 + threadIdx.x;    // over MROWS*D
    int d = (int)(idx & (D - 1));
    size_t m = idx >> 7;                                    // m = t*64 + b
    int t = (int)(m >> 6);
    int b = (int)(m & 63);
    int xi = __ldg(&x[(size_t)b * T + t]);
    g_e[idx] = (xi == 0) ? 0.f : __ldg(&table[(size_t)xi * D + d]);
}

// ------- xg0[t][col][b] = (e @ Wih0^T)[m][col] + bias0[col] ; K=128 ----------
__global__ void __launch_bounds__(256, 2) gemm_xg0(const float* __restrict__ Wih) {
    __shared__ float As[32][132];
    __shared__ float Bs[32][132];
    const int tid = threadIdx.x;
    const int tx = tid & 15, ty = tid >> 4;
    const size_t m0 = (size_t)blockIdx.y * 128;
    const int    n0 = blockIdx.x * 128;

    ull acc[4][8];
#pragma unroll
    for (int p = 0; p < 4; p++)
#pragma unroll
        for (int j = 0; j < 8; j++) acc[p][j] = 0ULL;

    for (int kc = 0; kc < D; kc += 32) {
        for (int i = tid; i < 128 * 32; i += 256) {
            int mm = i >> 5, k = i & 31;
            As[k][mm] = g_e[(m0 + mm) * D + kc + k];
        }
        for (int i = tid; i < 128 * 32; i += 256) {
            int nn = i >> 5, k = i & 31;
            Bs[k][nn] = Wih[(size_t)(n0 + nn) * D + kc + k];
        }
        __syncthreads();
#pragma unroll
        for (int k = 0; k < 32; k++) {
            ulonglong2 a01 = *(const ulonglong2*)&As[k][tx * 8];
            ulonglong2 a23 = *(const ulonglong2*)&As[k][tx * 8 + 4];
            float4 f0 = *(const float4*)&Bs[k][ty * 8];
            float4 f1 = *(const float4*)&Bs[k][ty * 8 + 4];
            ull bb[8];
            bb[0] = dup2(f0.x); bb[1] = dup2(f0.y); bb[2] = dup2(f0.z); bb[3] = dup2(f0.w);
            bb[4] = dup2(f1.x); bb[5] = dup2(f1.y); bb[6] = dup2(f1.z); bb[7] = dup2(f1.w);
#pragma unroll
            for (int j = 0; j < 8; j++) {
                FMA2(acc[0][j], a01.x, bb[j]);
                FMA2(acc[1][j], a01.y, bb[j]);
                FMA2(acc[2][j], a23.x, bb[j]);
                FMA2(acc[3][j], a23.y, bb[j]);
            }
        }
        __syncthreads();
    }
    const int tq = (int)(m0 >> 6) + (tx >> 3);
    const int bb0 = (tx & 7) * 8;
#pragma unroll
    for (int j = 0; j < 8; j++) {
        int col = n0 + ty * 8 + j;
        ull bd = dup2(g_bias0[col]);
        ull v0, v1, v2, v3;
        ADD2(v0, acc[0][j], bd); ADD2(v1, acc[1][j], bd);
        ADD2(v2, acc[2][j], bd); ADD2(v3, acc[3][j], bd);
        float* dst = g_xg0 + ((size_t)tq * G4 + col) * B + bb0;
        ulonglong2 q0; q0.x = v0; q0.y = v1;
        ulonglong2 q1; q1.x = v2; q1.y = v3;
        *(ulonglong2*)dst       = q0;
        *(ulonglong2*)(dst + 4) = q1;
    }
}

// ---------------- persistent pipelined 2-layer LSTM --------------------------
// dynamic SMEM: [0,32KB) weights (dup2), [32KB,64KB) reduction buffer
extern __shared__ char smem_raw[];

__global__ void __launch_bounds__(256, 2) lstm_kernel(
    const float* __restrict__ Whh0,
    const float* __restrict__ Wih1,
    const float* __restrict__ Whh1,
    const float* __restrict__ bih1,
    const float* __restrict__ bhh1)
{
    ull*   w_s2 = (ull*)smem_raw;               // L0: [16r][256k]  L1: [8r][512k]
    float* red  = (float*)(smem_raw + 32768);   // L0: [8ks][16r][64b]  L1: [16ks][8r][64b]
    const int bid = blockIdx.x, tid = threadIdx.x;
    const int wq = (tid >> 5) & 3;              // warp's quarter (warp-uniform)

    if (bid < NB_L0) {
        // ========== layer 0 : 4 j's -> 16 rows (r = g*4 + jl), K=256 =========
        const int j0 = bid * 4;
        for (int i = tid; i < 16 * 256; i += 256) {
            int r = i >> 8, k = i & 255;          // r = g*4 + jl
            int g = r >> 2, jl2 = r & 3;
            w_s2[i] = dup2(Whh0[(size_t)(g * 256 + j0 + jl2) * H + k]);
        }
        const int bg = tid & 15, ks = (tid >> 4) & 7, rg = tid >> 7;
        const int b0 = bg * 4, kbase = ks * 32, r0 = rg * 8;
        const int jl = tid >> 6, ab = tid & 63;   // activation: (j0+jl, ab)
        float c_reg = 0.f;
        __syncthreads();

        for (int t = 0; t < T; ++t) {
            // prefetch xg0 (DRAM) before any waiting
            const float* xgp = g_xg0 + ((size_t)t * G4 + j0 + jl) * B + ab;
            float xp0 = xgp[0];
            float xp1 = xgp[(size_t)256 * B];
            float xp2 = xgp[(size_t)512 * B];
            float xp3 = xgp[(size_t)768 * B];

            // warp covers h0 quarter wq; collectively all quarters covered
            if (t >= 1)    waitq(&g_done0q[t - 1][wq], NB_L0 / 4);
            if (t >= RING) waitq(&g_done1q[t - RING][wq], NB_L1 / 4);

            const float* hb = g_h0buf[(t + RING - 1) & (RING - 1)] + b0;
            ull acc0[8], acc1[8];
#pragma unroll
            for (int c = 0; c < 8; c++) { acc0[c] = 0ULL; acc1[c] = 0ULL; }

            ulonglong2 hv[2][4];
#pragma unroll
            for (int kc = 0; kc < 4; kc++)
                hv[0][kc] = *(const ulonglong2*)(hb + (size_t)(kbase + kc) * B);
#pragma unroll
            for (int it = 0; it < 8; ++it) {
                const int cur = it & 1, nxt = cur ^ 1;
                if (it < 7) {
#pragma unroll
                    for (int kc = 0; kc < 4; kc++)
                        hv[nxt][kc] = *(const ulonglong2*)(hb + (size_t)(kbase + (it + 1) * 4 + kc) * B);
                }
                const ull* wb = w_s2 + r0 * 256 + kbase + it * 4;
#pragma unroll
                for (int rr = 0; rr < 8; rr++) {
                    const ull* wr = wb + rr * 256;
                    ulonglong2 w01 = ((const ulonglong2*)wr)[0];
                    ulonglong2 w23 = ((const ulonglong2*)wr)[1];
                    FMA2(acc0[rr], hv[cur][0].x, w01.x); FMA2(acc1[rr], hv[cur][0].y, w01.x);
                    FMA2(acc0[rr], hv[cur][1].x, w01.y); FMA2(acc1[rr], hv[cur][1].y, w01.y);
                    FMA2(acc0[rr], hv[cur][2].x, w23.x); FMA2(acc1[rr], hv[cur][2].y, w23.x);
                    FMA2(acc0[rr], hv[cur][3].x, w23.y); FMA2(acc1[rr], hv[cur][3].y, w23.y);
                }
            }
#pragma unroll
            for (int rr = 0; rr < 8; rr++) {
                ulonglong2 v; v.x = acc0[rr]; v.y = acc1[rr];
                *(ulonglong2*)&red[ks * 1024 + (r0 + rr) * 64 + b0] = v;
            }
            __syncthreads();   // red complete; all warps passed waits -> h write safe

            {   // activation: one (b, jl) pair per thread (256 pairs, 256 threads)
                float s0 = xp0, s1 = xp1, s2 = xp2, s3 = xp3;
#pragma unroll
                for (int q = 0; q < 8; q++) {
                    const float* rp = red + q * 1024 + jl * 64 + ab;
                    s0 += rp[0]; s1 += rp[256]; s2 += rp[512]; s3 += rp[768];
                }
                c_reg = sigf(s1) * c_reg + sigf(s0) * tanh_f(s2);
                float hval = sigf(s3) * tanh_f(c_reg);
                g_h0buf[t & (RING - 1)][(j0 + jl) * B + ab] = hval;
            }
            __syncthreads();   // h writes + red reads complete
            if (tid == 0) arrive_rel(&g_done0q[t][bid >> 4]);
        }
    } else {
        // ========== layer 1 : 2 j's -> 8 rows (r = g*2 + jl), K=512 ==========
        const int lb = bid - NB_L0;
        const int j0 = lb * 2;
        for (int i = tid; i < 8 * 512; i += 256) {
            int r = i >> 9, k = i & 511;          // r = g*2 + jl
            int g = r >> 1, jl2 = r & 1;
            float w = (k < 256) ? Wih1[(size_t)(g * 256 + j0 + jl2) * H + k]
                                : Whh1[(size_t)(g * 256 + j0 + jl2) * H + (k - 256)];
            w_s2[i] = dup2(w);
        }
        const int bg = tid & 15, ks = tid >> 4;   // ks in [0,16), 32-k slices
        const int b0 = bg * 4;
        const int w8 = tid >> 5;                  // warp id 0..7
        const int jl = (tid >> 6) & 1, ab = tid & 63;
        float bi0 = 0.f, bi1 = 0.f, bi2 = 0.f, bi3 = 0.f;
        if (tid < 128) {
            bi0 = bih1[0 * 256 + j0 + jl] + bhh1[0 * 256 + j0 + jl];
            bi1 = bih1[1 * 256 + j0 + jl] + bhh1[1 * 256 + j0 + jl];
            bi2 = bih1[2 * 256 + j0 + jl] + bhh1[2 * 256 + j0 + jl];
            bi3 = bih1[3 * 256 + j0 + jl] + bhh1[3 * 256 + j0 + jl];
        }
        float c_reg = 0.f;
        __syncthreads();

        for (int tp = 0; tp < T; ++tp) {
            // warps 0-3 cover all h0 quarters; warps 4-7 all h1 quarters
            if (w8 < 4) {
                waitq(&g_done0q[tp][w8], NB_L0 / 4);
            } else if (tp >= 1) {
                waitq(&g_done1q[tp - 1][w8 - 4], NB_L1 / 4);
            }

            const float* hb;
            int kloc;
            if (ks < 8) { hb = g_h0buf[tp & (RING - 1)] + b0;              kloc = ks * 32; }
            else        { hb = g_h1buf[(tp + RING - 1) & (RING - 1)] + b0; kloc = (ks - 8) * 32; }

            ull acc0[8], acc1[8];
#pragma unroll
            for (int c = 0; c < 8; c++) { acc0[c] = 0ULL; acc1[c] = 0ULL; }

            ulonglong2 hv[2][4];
#pragma unroll
            for (int kc = 0; kc < 4; kc++)
                hv[0][kc] = *(const ulonglong2*)(hb + (size_t)(kloc + kc) * B);
#pragma unroll
            for (int it = 0; it < 8; ++it) {
                const int cur = it & 1, nxt = cur ^ 1;
                if (it < 7) {
#pragma unroll
                    for (int kc = 0; kc < 4; kc++)
                        hv[nxt][kc] = *(const ulonglong2*)(hb + (size_t)(kloc + (it + 1) * 4 + kc) * B);
                }
                const ull* wb = w_s2 + ks * 32 + it * 4;   // global k = ks*32 + it*4
#pragma unroll
                for (int rr = 0; rr < 8; rr++) {
                    const ull* wr = wb + rr * 512;
                    ulonglong2 w01 = ((const ulonglong2*)wr)[0];
                    ulonglong2 w23 = ((const ulonglong2*)wr)[1];
                    FMA2(acc0[rr], hv[cur][0].x, w01.x); FMA2(acc1[rr], hv[cur][0].y, w01.x);
                    FMA2(acc0[rr], hv[cur][1].x, w01.y); FMA2(acc1[rr], hv[cur][1].y, w01.y);
                    FMA2(acc0[rr], hv[cur][2].x, w23.x); FMA2(acc1[rr], hv[cur][2].y, w23.x);
                    FMA2(acc0[rr], hv[cur][3].x, w23.y); FMA2(acc1[rr], hv[cur][3].y, w23.y);
                }
            }
#pragma unroll
            for (int rr = 0; rr < 8; rr++) {
                ulonglong2 v; v.x = acc0[rr]; v.y = acc1[rr];
                *(ulonglong2*)&red[ks * 512 + rr * 64 + b0] = v;
            }
            __syncthreads();

            if (tid < 128) {   // activation: 2 j x 64 b = 128 pairs
                float s0 = bi0, s1 = bi1, s2 = bi2, s3 = bi3;
#pragma unroll
                for (int q = 0; q < 16; q++) {
                    const float* rp = red + q * 512 + jl * 64 + ab;
                    s0 += rp[0]; s1 += rp[128]; s2 += rp[256]; s3 += rp[384];
                }
                c_reg = sigf(s1) * c_reg + sigf(s0) * tanh_f(s2);
                float hval = sigf(s3) * tanh_f(c_reg);
                g_h1buf[tp & (RING - 1)][(j0 + jl) * B + ab] = hval;
                g_h1all[((size_t)tp * H + j0 + jl) * B + ab] = hval;
            }
            __syncthreads();
            if (tid == 0) arrive_rel(&g_done1q[tp][lb >> 5]);
        }
    }
}

// ------- FC: logits[m][o] = h1[m] . fcW[o] + fcb ; A = g_h1all[t][k][b] ------
__global__ void __launch_bounds__(256) gemm_fc(const float* __restrict__ fcW,
                                               const float* __restrict__ fcb) {
    __shared__ float As[32][132];
    __shared__ float Bs[32][68];
    const int tid = threadIdx.x;
    const int tx = tid & 15, ty = tid >> 4;
    const size_t m0 = (size_t)blockIdx.x * 128;
    const int t0 = (int)(m0 >> 6);

    float acc[8][4];
#pragma unroll
    for (int i = 0; i < 8; i++)
#pragma unroll
        for (int j = 0; j < 4; j++) acc[i][j] = 0.f;

    for (int kc = 0; kc < H; kc += 32) {
        for (int i = tid; i < 32 * 128; i += 256) {
            int k = i >> 7, mm = i & 127;
            int tq = t0 + (mm >> 6), b = mm & 63;
            As[k][mm] = g_h1all[(size_t)tq * (H * B) + (size_t)(kc + k) * B + b];
        }
        for (int i = tid; i < 64 * 32; i += 256) {
            int nn = i >> 5, k = i & 31;
            Bs[k][nn] = fcW[(size_t)nn * H + kc + k];
        }
        __syncthreads();
#pragma unroll
        for (int k = 0; k < 32; k++) {
            float a[8], bb[4];
#pragma unroll
            for (int i = 0; i < 8; i++) a[i] = As[k][ty * 8 + i];
#pragma unroll
            for (int j = 0; j < 4; j++) bb[j] = Bs[k][tx * 4 + j];
#pragma unroll
            for (int i = 0; i < 8; i++)
#pragma unroll
                for (int j = 0; j < 4; j++) acc[i][j] += a[i] * bb[j];
        }
        __syncthreads();
    }
#pragma unroll
    for (int i = 0; i < 8; i++) {
        size_t row = (m0 + ty * 8 + i) * OUTN + tx * 4;
#pragma unroll
        for (int j = 0; j < 4; j++)
            g_logits[row + j] = acc[i][j] + fcb[tx * 4 + j];
    }
}

// ---------------- softmax over 64, remap [t][b] -> out[b][t] -----------------
__global__ void softmax_kernel(float* __restrict__ out) {
    const int tid = threadIdx.x;
    const int lane = tid & 31, w = tid >> 5;
    size_t row = (size_t)blockIdx.x * 8 + w;   // row = t*64 + b
    const float* L = g_logits + row * OUTN;
    float v0 = L[lane], v1 = L[lane + 32];
    float mx = fmaxf(v0, v1);
#pragma unroll
    for (int off = 16; off; off >>= 1) mx = fmaxf(mx, __shfl_xor_sync(~0u, mx, off));
    float e0 = expf(v0 - mx), e1 = expf(v1 - mx);
    float s = e0 + e1;
#pragma unroll
    for (int off = 16; off; off >>= 1) s += __shfl_xor_sync(~0u, s, off);
    float inv = 1.f / s;
    int t = (int)(row >> 6), b = (int)(row & 63);
    float* O = out + ((size_t)b * T + t) * OUTN;
    O[lane]      = e0 * inv;
    O[lane + 32] = e1 * inv;
}

// ---------------- launch ------------------------------------------------------
extern "C" void kernel_launch(void* const* d_in, const int* in_sizes, int n_in,
                              void* d_out, int out_size) {
    const int*   x     = (const int*)d_in[0];
    const float* table = (const float*)d_in[1];
    const float* Wih0  = (const float*)d_in[2];
    const float* Whh0  = (const float*)d_in[3];
    const float* bih0  = (const float*)d_in[4];
    const float* bhh0  = (const float*)d_in[5];
    const float* Wih1  = (const float*)d_in[6];
    const float* Whh1  = (const float*)d_in[7];
    const float* bih1  = (const float*)d_in[8];
    const float* bhh1  = (const float*)d_in[9];
    const float* fcW   = (const float*)d_in[10];
    const float* fcb   = (const float*)d_in[11];
    float* out = (float*)d_out;

    // one-time (idempotent): allow 64KB dynamic SMEM on the persistent kernel.
    // Set during the correctness run; persists for the capture run (errors ignored).
    static int s_attr_done = 0;
    if (!s_attr_done) {
        cudaFuncSetAttribute(lstm_kernel,
                             cudaFuncAttributeMaxDynamicSharedMemorySize, 65536);
        s_attr_done = 1;
    }

    // reset counters + zero-state ring buffers every launch (graph-capturable)
    void *p0, *p1, *ph0, *ph1;
    cudaGetSymbolAddress(&p0,  g_done0q);
    cudaGetSymbolAddress(&p1,  g_done1q);
    cudaGetSymbolAddress(&ph0, g_h0buf);
    cudaGetSymbolAddress(&ph1, g_h1buf);
    cudaMemsetAsync(p0,  0, T * 4 * sizeof(int));
    cudaMemsetAsync(p1,  0, T * 4 * sizeof(int));
    cudaMemsetAsync(ph0, 0, RING * H * B * sizeof(float));
    cudaMemsetAsync(ph1, 0, RING * H * B * sizeof(float));

    prep_bias<<<4, 256>>>(bih0, bhh0);
    embed_kernel<<<(MROWS * D) / 256, 256>>>(x, table);
    gemm_xg0<<<dim3(8, MROWS / 128), 256>>>(Wih0);

    lstm_kernel<<<NBLK, 256, 65536>>>(Whh0, Wih1, Whh1, bih1, bhh1);

    gemm_fc<<<MROWS / 128, 256>>>(fcW, fcb);
    softmax_kernel<<<MROWS / 8, 256>>>(out);
}

// round 7
// speedup vs baseline: 1.4524x; 1.0093x over previous
#include <cuda_runtime.h>
#include <math.h>

#define B    64
#define T    2048
#define D    128
#define H    256
#define G4   1024
#define OUTN 64
#define MROWS (T * B)          // 131072
#define NB_L0 64               // layer-0 blocks (4 j each)
#define NB_L1 128              // layer-1 blocks (2 j each)
#define NBLK  (NB_L0 + NB_L1)  // 192
#define RING 4

typedef unsigned long long ull;

// ---------------- scratch ----------------------------------------------------
__device__ float g_e[(size_t)MROWS * D];           // [m][d]
__device__ float g_xg0[(size_t)MROWS * G4];        // [t][col][b]
__device__ float g_h1all[(size_t)MROWS * H];       // [t][j][b]
__device__ float g_logits[(size_t)MROWS * OUTN];   // [m][o]
__device__ float g_h0buf[RING][H * B];             // [ring][k][b]
__device__ float g_h1buf[RING][H * B];
__device__ float g_bias0[G4];
__device__ int   g_done0q[T][4];                   // block arrivals (16 per quarter)
__device__ int   g_done1q[T][4];                   // block arrivals (32 per quarter)

// ---------------- packed f32x2 helpers ---------------------------------------
#define FMA2(d, a, b) asm("fma.rn.f32x2 %0, %1, %2, %0;" : "+l"(d) : "l"(a), "l"(b))
#define ADD2(d, a, b) asm("add.rn.f32x2 %0, %1, %2;"     : "=l"(d) : "l"(a), "l"(b))
__device__ __forceinline__ ull dup2(float w) {
    ull d; unsigned u = __float_as_uint(w);
    asm("mov.b64 %0, {%1, %1};" : "=l"(d) : "r"(u));
    return d;
}

__device__ __forceinline__ float sigf(float x) { return 1.f / (1.f + __expf(-x)); }
__device__ __forceinline__ float tanh_f(float x) {
    float e = __expf(-2.f * fabsf(x));
    float r = (1.f - e) / (1.f + e);
    return copysignf(r, x);
}

__device__ __forceinline__ void waitq(const int* p, int thr) {
    int v;
    do {
        asm volatile("ld.global.acquire.gpu.b32 %0, [%1];" : "=r"(v) : "l"(p) : "memory");
    } while (v < thr);
}

__device__ __forceinline__ void arrive_rel(int* p) {
    asm volatile("red.release.gpu.global.add.u32 [%0], %1;" :: "l"(p), "r"(1) : "memory");
}

// ---------------- tiny kernels ------------------------------------------------
__global__ void prep_bias(const float* __restrict__ bih0, const float* __restrict__ bhh0) {
    int i = blockIdx.x * 256 + threadIdx.x;
    if (i < G4) g_bias0[i] = bih0[i] + bhh0[i];
}

__global__ void embed_kernel(const int* __restrict__ x, const float* __restrict__ table) {
    size_t idx = (size_t)blockIdx.x * 256 + threadIdx.x;    // over MROWS*D
    int d = (int)(idx & (D - 1));
    size_t m = idx >> 7;                                    // m = t*64 + b
    int t = (int)(m >> 6);
    int b = (int)(m & 63);
    int xi = __ldg(&x[(size_t)b * T + t]);
    g_e[idx] = (xi == 0) ? 0.f : __ldg(&table[(size_t)xi * D + d]);
}

// ------- xg0[t][col][b] = (e @ Wih0^T)[m][col] + bias0[col] ; K=128 ----------
__global__ void __launch_bounds__(256, 2) gemm_xg0(const float* __restrict__ Wih) {
    __shared__ float As[32][132];
    __shared__ float Bs[32][132];
    const int tid = threadIdx.x;
    const int tx = tid & 15, ty = tid >> 4;
    const size_t m0 = (size_t)blockIdx.y * 128;
    const int    n0 = blockIdx.x * 128;

    ull acc[4][8];
#pragma unroll
    for (int p = 0; p < 4; p++)
#pragma unroll
        for (int j = 0; j < 8; j++) acc[p][j] = 0ULL;

    for (int kc = 0; kc < D; kc += 32) {
        for (int i = tid; i < 128 * 32; i += 256) {
            int mm = i >> 5, k = i & 31;
            As[k][mm] = g_e[(m0 + mm) * D + kc + k];
        }
        for (int i = tid; i < 128 * 32; i += 256) {
            int nn = i >> 5, k = i & 31;
            Bs[k][nn] = Wih[(size_t)(n0 + nn) * D + kc + k];
        }
        __syncthreads();
#pragma unroll
        for (int k = 0; k < 32; k++) {
            ulonglong2 a01 = *(const ulonglong2*)&As[k][tx * 8];
            ulonglong2 a23 = *(const ulonglong2*)&As[k][tx * 8 + 4];
            float4 f0 = *(const float4*)&Bs[k][ty * 8];
            float4 f1 = *(const float4*)&Bs[k][ty * 8 + 4];
            ull bb[8];
            bb[0] = dup2(f0.x); bb[1] = dup2(f0.y); bb[2] = dup2(f0.z); bb[3] = dup2(f0.w);
            bb[4] = dup2(f1.x); bb[5] = dup2(f1.y); bb[6] = dup2(f1.z); bb[7] = dup2(f1.w);
#pragma unroll
            for (int j = 0; j < 8; j++) {
                FMA2(acc[0][j], a01.x, bb[j]);
                FMA2(acc[1][j], a01.y, bb[j]);
                FMA2(acc[2][j], a23.x, bb[j]);
                FMA2(acc[3][j], a23.y, bb[j]);
            }
        }
        __syncthreads();
    }
    const int tq = (int)(m0 >> 6) + (tx >> 3);
    const int bb0 = (tx & 7) * 8;
#pragma unroll
    for (int j = 0; j < 8; j++) {
        int col = n0 + ty * 8 + j;
        ull bd = dup2(g_bias0[col]);
        ull v0, v1, v2, v3;
        ADD2(v0, acc[0][j], bd); ADD2(v1, acc[1][j], bd);
        ADD2(v2, acc[2][j], bd); ADD2(v3, acc[3][j], bd);
        float* dst = g_xg0 + ((size_t)tq * G4 + col) * B + bb0;
        ulonglong2 q0; q0.x = v0; q0.y = v1;
        ulonglong2 q1; q1.x = v2; q1.y = v3;
        *(ulonglong2*)dst       = q0;
        *(ulonglong2*)(dst + 4) = q1;
    }
}

// ---------------- persistent pipelined 2-layer LSTM --------------------------
// dynamic SMEM: [0,32KB) weights (dup2), [32KB,64KB) reduction buffer
extern __shared__ char smem_raw[];

__global__ void __launch_bounds__(256, 2) lstm_kernel(
    const float* __restrict__ Whh0,
    const float* __restrict__ Wih1,
    const float* __restrict__ Whh1,
    const float* __restrict__ bih1,
    const float* __restrict__ bhh1)
{
    ull*   w_s2 = (ull*)smem_raw;               // L0: [16r][256k]  L1: [8r][512k]
    float* red  = (float*)(smem_raw + 32768);   // L0: [8ks][16r][64b]  L1: [16ks][8r][64b]
    const int bid = blockIdx.x, tid = threadIdx.x;
    const int wq = (tid >> 5) & 3;              // warp's quarter (warp-uniform)

    if (bid < NB_L0) {
        // ========== layer 0 : 4 j's -> 16 rows (r = g*4 + jl), K=256 =========
        const int j0 = bid * 4;
        for (int i = tid; i < 16 * 256; i += 256) {
            int r = i >> 8, k = i & 255;          // r = g*4 + jl
            int g = r >> 2, jl2 = r & 3;
            w_s2[i] = dup2(Whh0[(size_t)(g * 256 + j0 + jl2) * H + k]);
        }
        const int bg = tid & 15, ks = (tid >> 4) & 7, rg = tid >> 7;
        const int b0 = bg * 4, kbase = ks * 32, r0 = rg * 8;
        const int jl = tid >> 6, ab = tid & 63;   // activation: (j0+jl, ab)
        float c_reg = 0.f;
        __syncthreads();

        for (int t = 0; t < T; ++t) {
            // prefetch xg0 (DRAM) before any waiting
            const float* xgp = g_xg0 + ((size_t)t * G4 + j0 + jl) * B + ab;
            float xp0 = xgp[0];
            float xp1 = xgp[(size_t)256 * B];
            float xp2 = xgp[(size_t)512 * B];
            float xp3 = xgp[(size_t)768 * B];

            // warp covers h0 quarter wq; collectively all quarters covered
            if (t >= 1)    waitq(&g_done0q[t - 1][wq], NB_L0 / 4);
            if (t >= RING) waitq(&g_done1q[t - RING][wq], NB_L1 / 4);

            const float* hb = g_h0buf[(t + RING - 1) & (RING - 1)] + b0;
            ull acc0[8], acc1[8];
#pragma unroll
            for (int c = 0; c < 8; c++) { acc0[c] = 0ULL; acc1[c] = 0ULL; }

            ulonglong2 hv[2][4];
#pragma unroll
            for (int kc = 0; kc < 4; kc++)
                hv[0][kc] = *(const ulonglong2*)(hb + (size_t)(kbase + kc) * B);
#pragma unroll
            for (int it = 0; it < 8; ++it) {
                const int cur = it & 1, nxt = cur ^ 1;
                if (it < 7) {
#pragma unroll
                    for (int kc = 0; kc < 4; kc++)
                        hv[nxt][kc] = *(const ulonglong2*)(hb + (size_t)(kbase + (it + 1) * 4 + kc) * B);
                }
                const ull* wb = w_s2 + r0 * 256 + kbase + it * 4;
#pragma unroll
                for (int rr = 0; rr < 8; rr++) {
                    const ull* wr = wb + rr * 256;
                    ulonglong2 w01 = ((const ulonglong2*)wr)[0];
                    ulonglong2 w23 = ((const ulonglong2*)wr)[1];
                    FMA2(acc0[rr], hv[cur][0].x, w01.x); FMA2(acc1[rr], hv[cur][0].y, w01.x);
                    FMA2(acc0[rr], hv[cur][1].x, w01.y); FMA2(acc1[rr], hv[cur][1].y, w01.y);
                    FMA2(acc0[rr], hv[cur][2].x, w23.x); FMA2(acc1[rr], hv[cur][2].y, w23.x);
                    FMA2(acc0[rr], hv[cur][3].x, w23.y); FMA2(acc1[rr], hv[cur][3].y, w23.y);
                }
            }
#pragma unroll
            for (int rr = 0; rr < 8; rr++) {
                ulonglong2 v; v.x = acc0[rr]; v.y = acc1[rr];
                *(ulonglong2*)&red[ks * 1024 + (r0 + rr) * 64 + b0] = v;
            }
            __syncthreads();   // red complete; all warps passed waits -> h write safe

            {   // activation: one (b, jl) pair per thread (256 pairs, 256 threads)
                float s0 = xp0, s1 = xp1, s2 = xp2, s3 = xp3;
#pragma unroll
                for (int q = 0; q < 8; q++) {
                    const float* rp = red + q * 1024 + jl * 64 + ab;
                    s0 += rp[0]; s1 += rp[256]; s2 += rp[512]; s3 += rp[768];
                }
                c_reg = sigf(s1) * c_reg + sigf(s0) * tanh_f(s2);
                float hval = sigf(s3) * tanh_f(c_reg);
                g_h0buf[t & (RING - 1)][(j0 + jl) * B + ab] = hval;
            }
            __syncthreads();   // h writes + red reads complete
            if (tid == 0) arrive_rel(&g_done0q[t][bid >> 4]);
        }
    } else {
        // ========== layer 1 : 2 j's -> 8 rows (r = g*2 + jl), K=512 ==========
        const int lb = bid - NB_L0;
        const int j0 = lb * 2;
        for (int i = tid; i < 8 * 512; i += 256) {
            int r = i >> 9, k = i & 511;          // r = g*2 + jl
            int g = r >> 1, jl2 = r & 1;
            float w = (k < 256) ? Wih1[(size_t)(g * 256 + j0 + jl2) * H + k]
                                : Whh1[(size_t)(g * 256 + j0 + jl2) * H + (k - 256)];
            w_s2[i] = dup2(w);
        }
        const int bg = tid & 15, ks = tid >> 4;   // ks in [0,16), 32-k slices
        const int b0 = bg * 4;
        const int w8 = tid >> 5;                  // warp id 0..7
        const int jl = (tid >> 6) & 1, ab = tid & 63;
        float bi0 = 0.f, bi1 = 0.f, bi2 = 0.f, bi3 = 0.f;
        if (tid < 128) {
            bi0 = bih1[0 * 256 + j0 + jl] + bhh1[0 * 256 + j0 + jl];
            bi1 = bih1[1 * 256 + j0 + jl] + bhh1[1 * 256 + j0 + jl];
            bi2 = bih1[2 * 256 + j0 + jl] + bhh1[2 * 256 + j0 + jl];
            bi3 = bih1[3 * 256 + j0 + jl] + bhh1[3 * 256 + j0 + jl];
        }
        float c_reg = 0.f;
        __syncthreads();

        for (int tp = 0; tp < T; ++tp) {
            // warps 0-3 cover all h0 quarters; warps 4-7 all h1 quarters
            if (w8 < 4) {
                waitq(&g_done0q[tp][w8], NB_L0 / 4);
            } else if (tp >= 1) {
                waitq(&g_done1q[tp - 1][w8 - 4], NB_L1 / 4);
            }

            const float* hb;
            int kloc;
            if (ks < 8) { hb = g_h0buf[tp & (RING - 1)] + b0;              kloc = ks * 32; }
            else        { hb = g_h1buf[(tp + RING - 1) & (RING - 1)] + b0; kloc = (ks - 8) * 32; }

            ull acc0[8], acc1[8];
#pragma unroll
            for (int c = 0; c < 8; c++) { acc0[c] = 0ULL; acc1[c] = 0ULL; }

            ulonglong2 hv[2][4];
#pragma unroll
            for (int kc = 0; kc < 4; kc++)
                hv[0][kc] = *(const ulonglong2*)(hb + (size_t)(kloc + kc) * B);
#pragma unroll
            for (int it = 0; it < 8; ++it) {
                const int cur = it & 1, nxt = cur ^ 1;
                if (it < 7) {
#pragma unroll
                    for (int kc = 0; kc < 4; kc++)
                        hv[nxt][kc] = *(const ulonglong2*)(hb + (size_t)(kloc + (it + 1) * 4 + kc) * B);
                }
                const ull* wb = w_s2 + ks * 32 + it * 4;   // global k = ks*32 + it*4
#pragma unroll
                for (int rr = 0; rr < 8; rr++) {
                    const ull* wr = wb + rr * 512;
                    ulonglong2 w01 = ((const ulonglong2*)wr)[0];
                    ulonglong2 w23 = ((const ulonglong2*)wr)[1];
                    FMA2(acc0[rr], hv[cur][0].x, w01.x); FMA2(acc1[rr], hv[cur][0].y, w01.x);
                    FMA2(acc0[rr], hv[cur][1].x, w01.y); FMA2(acc1[rr], hv[cur][1].y, w01.y);
                    FMA2(acc0[rr], hv[cur][2].x, w23.x); FMA2(acc1[rr], hv[cur][2].y, w23.x);
                    FMA2(acc0[rr], hv[cur][3].x, w23.y); FMA2(acc1[rr], hv[cur][3].y, w23.y);
                }
            }
#pragma unroll
            for (int rr = 0; rr < 8; rr++) {
                ulonglong2 v; v.x = acc0[rr]; v.y = acc1[rr];
                *(ulonglong2*)&red[ks * 512 + rr * 64 + b0] = v;
            }
            __syncthreads();

            if (tid < 128) {   // activation: 2 j x 64 b = 128 pairs
                float s0 = bi0, s1 = bi1, s2 = bi2, s3 = bi3;
#pragma unroll
                for (int q = 0; q < 16; q++) {
                    const float* rp = red + q * 512 + jl * 64 + ab;
                    s0 += rp[0]; s1 += rp[128]; s2 += rp[256]; s3 += rp[384];
                }
                c_reg = sigf(s1) * c_reg + sigf(s0) * tanh_f(s2);
                float hval = sigf(s3) * tanh_f(c_reg);
                g_h1buf[tp & (RING - 1)][(j0 + jl) * B + ab] = hval;
                g_h1all[((size_t)tp * H + j0 + jl) * B + ab] = hval;
            }
            __syncthreads();
            if (tid == 0) arrive_rel(&g_done1q[tp][lb >> 5]);
        }
    }
}

// ------- FC: logits[m][o] = h1[m] . fcW[o] + fcb ; A = g_h1all[t][k][b] ------
__global__ void __launch_bounds__(256) gemm_fc(const float* __restrict__ fcW,
                                               const float* __restrict__ fcb) {
    __shared__ float As[32][132];
    __shared__ float Bs[32][68];
    const int tid = threadIdx.x;
    const int tx = tid & 15, ty = tid >> 4;
    const size_t m0 = (size_t)blockIdx.x * 128;
    const int t0 = (int)(m0 >> 6);

    float acc[8][4];
#pragma unroll
    for (int i = 0; i < 8; i++)
#pragma unroll
        for (int j = 0; j < 4; j++) acc[i][j] = 0.f;

    for (int kc = 0; kc < H; kc += 32) {
        for (int i = tid; i < 32 * 128; i += 256) {
            int k = i >> 7, mm = i & 127;
            int tq = t0 + (mm >> 6), b = mm & 63;
            As[k][mm] = g_h1all[(size_t)tq * (H * B) + (size_t)(kc + k) * B + b];
        }
        for (int i = tid; i < 64 * 32; i += 256) {
            int nn = i >> 5, k = i & 31;
            Bs[k][nn] = fcW[(size_t)nn * H + kc + k];
        }
        __syncthreads();
#pragma unroll
        for (int k = 0; k < 32; k++) {
            float a[8], bb[4];
#pragma unroll
            for (int i = 0; i < 8; i++) a[i] = As[k][ty * 8 + i];
#pragma unroll
            for (int j = 0; j < 4; j++) bb[j] = Bs[k][tx * 4 + j];
#pragma unroll
            for (int i = 0; i < 8; i++)
#pragma unroll
                for (int j = 0; j < 4; j++) acc[i][j] += a[i] * bb[j];
        }
        __syncthreads();
    }
#pragma unroll
    for (int i = 0; i < 8; i++) {
        size_t row = (m0 + ty * 8 + i) * OUTN + tx * 4;
#pragma unroll
        for (int j = 0; j < 4; j++)
            g_logits[row + j] = acc[i][j] + fcb[tx * 4 + j];
    }
}

// ---------------- softmax over 64, remap [t][b] -> out[b][t] -----------------
__global__ void softmax_kernel(float* __restrict__ out) {
    const int tid = threadIdx.x;
    const int lane = tid & 31, w = tid >> 5;
    size_t row = (size_t)blockIdx.x * 8 + w;   // row = t*64 + b
    const float* L = g_logits + row * OUTN;
    float v0 = L[lane], v1 = L[lane + 32];
    float mx = fmaxf(v0, v1);
#pragma unroll
    for (int off = 16; off; off >>= 1) mx = fmaxf(mx, __shfl_xor_sync(~0u, mx, off));
    float e0 = expf(v0 - mx), e1 = expf(v1 - mx);
    float s = e0 + e1;
#pragma unroll
    for (int off = 16; off; off >>= 1) s += __shfl_xor_sync(~0u, s, off);
    float inv = 1.f / s;
    int t = (int)(row >> 6), b = (int)(row & 63);
    float* O = out + ((size_t)b * T + t) * OUTN;
    O[lane]      = e0 * inv;
    O[lane + 32] = e1 * inv;
}

// ---------------- launch ------------------------------------------------------
extern "C" void kernel_launch(void* const* d_in, const int* in_sizes, int n_in,
                              void* d_out, int out_size) {
    const int*   x     = (const int*)d_in[0];
    const float* table = (const float*)d_in[1];
    const float* Wih0  = (const float*)d_in[2];
    const float* Whh0  = (const float*)d_in[3];
    const float* bih0  = (const float*)d_in[4];
    const float* bhh0  = (const float*)d_in[5];
    const float* Wih1  = (const float*)d_in[6];
    const float* Whh1  = (const float*)d_in[7];
    const float* bih1  = (const float*)d_in[8];
    const float* bhh1  = (const float*)d_in[9];
    const float* fcW   = (const float*)d_in[10];
    const float* fcb   = (const float*)d_in[11];
    float* out = (float*)d_out;

    // one-time (idempotent): allow 64KB dynamic SMEM on the persistent kernel.
    // Set during the correctness run; persists for the capture run (errors ignored).
    static int s_attr_done = 0;
    if (!s_attr_done) {
        cudaFuncSetAttribute(lstm_kernel,
                             cudaFuncAttributeMaxDynamicSharedMemorySize, 65536);
        s_attr_done = 1;
    }

    // reset counters + zero-state ring buffers every launch (graph-capturable)
    void *p0, *p1, *ph0, *ph1;
    cudaGetSymbolAddress(&p0,  g_done0q);
    cudaGetSymbolAddress(&p1,  g_done1q);
    cudaGetSymbolAddress(&ph0, g_h0buf);
    cudaGetSymbolAddress(&ph1, g_h1buf);
    cudaMemsetAsync(p0,  0, T * 4 * sizeof(int));
    cudaMemsetAsync(p1,  0, T * 4 * sizeof(int));
    cudaMemsetAsync(ph0, 0, RING * H * B * sizeof(float));
    cudaMemsetAsync(ph1, 0, RING * H * B * sizeof(float));

    prep_bias<<<4, 256>>>(bih0, bhh0);
    embed_kernel<<<(MROWS * D) / 256, 256>>>(x, table);
    gemm_xg0<<<dim3(8, MROWS / 128), 256>>>(Wih0);

    lstm_kernel<<<NBLK, 256, 65536>>>(Whh0, Wih1, Whh1, bih1, bhh1);

    gemm_fc<<<MROWS / 128, 256>>>(fcW, fcb);
    softmax_kernel<<<MROWS / 8, 256>>>(out);
}

// round 10
// speedup vs baseline: 2.2132x; 1.5238x over previous
#include <cuda_runtime.h>
#include <cuda_fp16.h>
#include <math.h>
#include <stdint.h>

#define B    64
#define T    2048
#define D    128
#define H    256
#define G4   1024
#define OUTN 64
#define MROWS (T * B)
#define NB_L0 64
#define NB_L1 64
#define NBLK  (NB_L0 + NB_L1)
#define RING 4

typedef unsigned long long ull;

// dynamic SMEM layout (bytes):
//   A (weights fp16, padded row-major) @ 0        (L1: 64 x 520 halves = 66560)
//   Bt (h fp16, [n][k] padded)         @ 66560    (L1: 16 x 520 halves = 16640)
//   red (gate exchange f32)            @ 83200    (64 x 17 floats = 4352)
#define OFF_B   66560
#define OFF_RED 83200
#define SMEM_BYTES 87552

// ---------------- scratch ------------------------------------------------------
__device__ float  g_e[(size_t)MROWS * D];
__device__ float  g_xg0[(size_t)MROWS * G4];        // [m][col] (includes bias0)
__device__ float  g_h1all[(size_t)MROWS * H];       // [m][k] row-major
__device__ float  g_logits[(size_t)MROWS * OUTN];
__device__ __half g_h0buf[RING][B * H];             // [ring][b][k]
__device__ __half g_h1buf[RING][B * H];
__device__ float  g_bias0[G4];
__device__ float  g_bias1[G4];
__device__ int    g_done0q[T][4];                   // 16 block-arrivals each
__device__ int    g_done1q[T][4];

// ---------------- f32x2 helpers (xg0 GEMM) --------------------------------------
#define FMA2(d, a, b) asm("fma.rn.f32x2 %0, %1, %2, %0;" : "+l"(d) : "l"(a), "l"(b))
#define ADD2(d, a, b) asm("add.rn.f32x2 %0, %1, %2;"     : "=l"(d) : "l"(a), "l"(b))
__device__ __forceinline__ ull dup2(float w) {
    ull d; unsigned u = __float_as_uint(w);
    asm("mov.b64 %0, {%1, %1};" : "=l"(d) : "r"(u));
    return d;
}

__device__ __forceinline__ float sigf(float x) { return 1.f / (1.f + __expf(-x)); }
__device__ __forceinline__ float tanh_f(float x) {
    float e = __expf(-2.f * fabsf(x));
    return copysignf((1.f - e) / (1.f + e), x);
}

__device__ __forceinline__ void waitq(const int* p, int thr) {
    int v;
    do {
        asm volatile("ld.global.acquire.gpu.b32 %0, [%1];" : "=r"(v) : "l"(p) : "memory");
    } while (v < thr);
}
__device__ __forceinline__ void arrive_rel(int* p) {
    asm volatile("red.release.gpu.global.add.u32 [%0], %1;" :: "l"(p), "r"(1) : "memory");
}

// ---------------- warp MMA helpers -----------------------------------------------
__device__ __forceinline__ uint32_t smem_u32(const void* p) {
    uint32_t a;
    asm("{ .reg .u64 t; cvta.to.shared.u64 t, %1; cvt.u32.u64 %0, t; }" : "=r"(a) : "l"(p));
    return a;
}
__device__ __forceinline__ void ldsm_x4(uint32_t& a0, uint32_t& a1, uint32_t& a2,
                                        uint32_t& a3, uint32_t addr) {
    asm volatile("ldmatrix.sync.aligned.m8n8.x4.shared.b16 {%0,%1,%2,%3}, [%4];"
                 : "=r"(a0), "=r"(a1), "=r"(a2), "=r"(a3) : "r"(addr));
}
__device__ __forceinline__ void ldsm_x2(uint32_t& b0, uint32_t& b1, uint32_t addr) {
    asm volatile("ldmatrix.sync.aligned.m8n8.x2.shared.b16 {%0,%1}, [%2];"
                 : "=r"(b0), "=r"(b1) : "r"(addr));
}
__device__ __forceinline__ void mma16816(float* d, uint32_t a0, uint32_t a1,
                                         uint32_t a2, uint32_t a3,
                                         uint32_t b0, uint32_t b1) {
    asm volatile(
        "mma.sync.aligned.m16n8k16.row.col.f32.f16.f16.f32 "
        "{%0,%1,%2,%3}, {%4,%5,%6,%7}, {%8,%9}, {%0,%1,%2,%3};"
        : "+f"(d[0]), "+f"(d[1]), "+f"(d[2]), "+f"(d[3])
        : "r"(a0), "r"(a1), "r"(a2), "r"(a3), "r"(b0), "r"(b1));
}

// ---------------- tiny kernels -----------------------------------------------------
__global__ void prep_bias(const float* __restrict__ bih0, const float* __restrict__ bhh0,
                          const float* __restrict__ bih1, const float* __restrict__ bhh1) {
    int i = blockIdx.x * 256 + threadIdx.x;
    if (i < G4) {
        g_bias0[i] = bih0[i] + bhh0[i];
        g_bias1[i] = bih1[i] + bhh1[i];
    }
}

__global__ void embed_kernel(const int* __restrict__ x, const float* __restrict__ table) {
    size_t idx = (size_t)blockIdx.x * 256 + threadIdx.x;
    int d = (int)(idx & (D - 1));
    size_t m = idx >> 7;
    int t = (int)(m >> 6);
    int b = (int)(m & 63);
    int xi = __ldg(&x[(size_t)b * T + t]);
    g_e[idx] = (xi == 0) ? 0.f : __ldg(&table[(size_t)xi * D + d]);
}

// ------- xg0[m][col] = (e @ Wih0^T)[m][col] + bias0[col] ; K=128 -------------------
__global__ void __launch_bounds__(256, 2) gemm_xg0(const float* __restrict__ Wih) {
    __shared__ float As[32][132];
    __shared__ float Bs[32][132];
    const int tid = threadIdx.x;
    const int tx = tid & 15, ty = tid >> 4;
    const size_t m0 = (size_t)blockIdx.y * 128;
    const int    n0 = blockIdx.x * 128;

    ull acc[8][4];
#pragma unroll
    for (int i = 0; i < 8; i++)
#pragma unroll
        for (int j = 0; j < 4; j++) acc[i][j] = 0ULL;

    for (int kc = 0; kc < D; kc += 32) {
        for (int i = tid; i < 128 * 32; i += 256) {
            int mm = i >> 5, k = i & 31;
            As[k][mm] = g_e[(m0 + mm) * D + kc + k];
        }
        for (int i = tid; i < 128 * 32; i += 256) {
            int nn = i >> 5, k = i & 31;
            Bs[k][nn] = Wih[(size_t)(n0 + nn) * D + kc + k];
        }
        __syncthreads();
#pragma unroll
        for (int k = 0; k < 32; k++) {
            ulonglong2 b01 = *(const ulonglong2*)&Bs[k][ty * 8];
            ulonglong2 b23 = *(const ulonglong2*)&Bs[k][ty * 8 + 4];
            float4 a0 = *(const float4*)&As[k][tx * 8];
            float4 a1 = *(const float4*)&As[k][tx * 8 + 4];
            float av[8] = {a0.x, a0.y, a0.z, a0.w, a1.x, a1.y, a1.z, a1.w};
#pragma unroll
            for (int i = 0; i < 8; i++) {
                ull ad = dup2(av[i]);
                FMA2(acc[i][0], ad, b01.x);
                FMA2(acc[i][1], ad, b01.y);
                FMA2(acc[i][2], ad, b23.x);
                FMA2(acc[i][3], ad, b23.y);
            }
        }
        __syncthreads();
    }
    ulonglong2 bp0 = *(const ulonglong2*)&g_bias0[n0 + ty * 8];
    ulonglong2 bp1 = *(const ulonglong2*)&g_bias0[n0 + ty * 8 + 4];
#pragma unroll
    for (int i = 0; i < 8; i++) {
        ull v0, v1, v2, v3;
        ADD2(v0, acc[i][0], bp0.x); ADD2(v1, acc[i][1], bp0.y);
        ADD2(v2, acc[i][2], bp1.x); ADD2(v3, acc[i][3], bp1.y);
        float* dst = g_xg0 + (m0 + tx * 8 + i) * G4 + n0 + ty * 8;
        ulonglong2 q0; q0.x = v0; q0.y = v1;
        ulonglong2 q1; q1.x = v2; q1.y = v3;
        *(ulonglong2*)dst       = q0;
        *(ulonglong2*)(dst + 4) = q1;
    }
}

// ---------------- persistent HMMA 2-layer LSTM --------------------------------------
// CTA tile: 16 j x 16 b. M=64 gate rows (r = g*16+jj), N=16, K=256/512.
extern __shared__ __align__(1024) char smem_raw[];

__global__ void __launch_bounds__(256, 1) lstm_kernel(
    const float* __restrict__ Whh0,
    const float* __restrict__ Wih1,
    const float* __restrict__ Whh1)
{
    float* red = (float*)(smem_raw + OFF_RED);   // [64][17]
    const uint32_t sbase = smem_u32(smem_raw);
    const int bid = blockIdx.x, tid = threadIdx.x;
    const int warp = tid >> 5, lane = tid & 31;

    const bool isL0 = bid < NB_L0;
    const int lb = isL0 ? bid : bid - NB_L0;
    const int jg = lb >> 2, bg = lb & 3;
    const int j0 = jg * 16, b0 = bg * 16;
    const int K  = isL0 ? 256 : 512;
    const int SA = isL0 ? 264 : 520;             // padded stride in halves

    // ---- load weights fp16 into SMEM (rows r = g*16+jj, cols k) ----
    {
        __half* A_s = (__half*)smem_raw;
        for (int i = tid; i < 64 * K; i += 256) {
            int r = i / K, k = i - r * K;
            int grow = (r >> 4) * 256 + j0 + (r & 15);
            float w;
            if (isL0)          w = Whh0[(size_t)grow * H + k];
            else if (k < 256)  w = Wih1[(size_t)grow * H + k];
            else               w = Whh1[(size_t)grow * H + (k - 256)];
            A_s[r * SA + k] = __float2half_rn(w);
        }
    }

    // warp tile: r0 = (warp&3)*16 rows, n0 = (warp>>2)*8 cols
    const int r0 = (warp & 3) * 16, n0w = (warp >> 2) * 8;
    const uint32_t aA = sbase + 2u * (uint32_t)((r0 + (lane & 15)) * SA + ((lane >> 4) << 3));
    const int blane = lane & 15;
    const uint32_t aB = sbase + OFF_B +
        2u * (uint32_t)(((n0w + (blane & 7)) * SA) + (((blane >> 3) & 1) << 3));

    // activation mapping: thread = bl*16 + jj  (jj fast for coalesced h stores)
    const int jj = tid & 15, bl = tid >> 4;
    float c_reg = 0.f;
    float bi[4];
    if (!isL0) {
#pragma unroll
        for (int g = 0; g < 4; g++) bi[g] = g_bias1[g * 256 + j0 + jj];
    }
    __syncthreads();   // A ready

    const uint32_t SBb = 2u * (uint32_t)SA;      // B row stride bytes

    for (int t = 0; t < T; ++t) {
        // ---- prefetch xg0 (L0) before any waiting ----
        float xp[4];
        if (isL0) {
            const float* xg = g_xg0 + ((size_t)t * B + b0 + bl) * G4 + j0 + jj;
#pragma unroll
            for (int g = 0; g < 4; g++) xp[g] = xg[g * 256];
        }

        // ---- waits + B fill ----
        char* smB = smem_raw + OFF_B;
        if (isL0) {
            if (t >= 1)    waitq(&g_done0q[t - 1][bg], 16);
            if (t >= RING) waitq(&g_done1q[t - RING][bg], 16);
            const __half* hsrc = g_h0buf[(t + RING - 1) & (RING - 1)];
#pragma unroll
            for (int rep = 0; rep < 2; rep++) {
                int c = rep * 256 + tid;        // 512 chunks of 16B
                int n = c >> 5, u = c & 31;
                uint4 v = *(const uint4*)(hsrc + (size_t)(b0 + n) * 256 + u * 8);
                *(uint4*)(smB + n * SBb + u * 16) = v;
            }
        } else {
            if (t >= 1) waitq(&g_done1q[t - 1][bg], 16);
            const __half* h1s = g_h1buf[(t + RING - 1) & (RING - 1)];
#pragma unroll
            for (int rep = 0; rep < 2; rep++) {
                int c = rep * 256 + tid;
                int n = c >> 5, u = c & 31;
                uint4 v = *(const uint4*)(h1s + (size_t)(b0 + n) * 256 + u * 8);
                *(uint4*)(smB + n * SBb + 512 + u * 16) = v;   // cols 256..511
            }
            waitq(&g_done0q[t][bg], 16);
            const __half* h0s = g_h0buf[t & (RING - 1)];
#pragma unroll
            for (int rep = 0; rep < 2; rep++) {
                int c = rep * 256 + tid;
                int n = c >> 5, u = c & 31;
                uint4 v = *(const uint4*)(h0s + (size_t)(b0 + n) * 256 + u * 8);
                *(uint4*)(smB + n * SBb + u * 16) = v;         // cols 0..255
            }
        }
        __syncthreads();   // B ready; all warps' waits passed -> h writes later safe

        // ---- MMA: one m16n8 tile per warp over K ----
        float d[4] = {0.f, 0.f, 0.f, 0.f};
        const int ksteps = K >> 4;
#pragma unroll 8
        for (int kk = 0; kk < ksteps; kk++) {
            uint32_t a0, a1, a2, a3, bb0, bb1;
            ldsm_x4(a0, a1, a2, a3, aA + kk * 32);
            ldsm_x2(bb0, bb1, aB + kk * 32);
            mma16816(d, a0, a1, a2, a3, bb0, bb1);
        }
        // store fragments to red[row][col]
        {
            int row = r0 + (lane >> 2);
            int col = n0w + (lane & 3) * 2;
            red[row * 17 + col]       = d[0];
            red[row * 17 + col + 1]   = d[1];
            red[(row + 8) * 17 + col]     = d[2];
            red[(row + 8) * 17 + col + 1] = d[3];
        }
        __syncthreads();

        // ---- activation: one (jj, bl) pair per thread ----
        {
            float s0, s1, s2, s3;
            if (isL0) {
                s0 = xp[0] + red[(jj)      * 17 + bl];
                s1 = xp[1] + red[(16 + jj) * 17 + bl];
                s2 = xp[2] + red[(32 + jj) * 17 + bl];
                s3 = xp[3] + red[(48 + jj) * 17 + bl];
            } else {
                s0 = bi[0] + red[(jj)      * 17 + bl];
                s1 = bi[1] + red[(16 + jj) * 17 + bl];
                s2 = bi[2] + red[(32 + jj) * 17 + bl];
                s3 = bi[3] + red[(48 + jj) * 17 + bl];
            }
            c_reg = sigf(s1) * c_reg + sigf(s0) * tanh_f(s2);
            float hval = sigf(s3) * tanh_f(c_reg);
            __half hv16 = __float2half_rn(hval);
            if (isL0) {
                g_h0buf[t & (RING - 1)][(size_t)(b0 + bl) * 256 + j0 + jj] = hv16;
            } else {
                g_h1buf[t & (RING - 1)][(size_t)(b0 + bl) * 256 + j0 + jj] = hv16;
                g_h1all[((size_t)t * B + b0 + bl) * H + j0 + jj] = hval;
            }
        }
        __syncthreads();
        if (tid == 0) {
            if (isL0) arrive_rel(&g_done0q[t][bg]);
            else      arrive_rel(&g_done1q[t][bg]);
        }
    }
}

// ------- FC: logits[m][o] = h1[m] . fcW[o] + fcb ; h1all is [m][k] -----------------
__global__ void __launch_bounds__(256) gemm_fc(const float* __restrict__ fcW,
                                               const float* __restrict__ fcb) {
    __shared__ float As[32][132];
    __shared__ float Bs[32][68];
    const int tid = threadIdx.x;
    const int tx = tid & 15, ty = tid >> 4;
    const size_t m0 = (size_t)blockIdx.x * 128;

    float acc[8][4];
#pragma unroll
    for (int i = 0; i < 8; i++)
#pragma unroll
        for (int j = 0; j < 4; j++) acc[i][j] = 0.f;

    for (int kc = 0; kc < H; kc += 32) {
        for (int i = tid; i < 128 * 32; i += 256) {
            int mm = i >> 5, k = i & 31;
            As[k][mm] = g_h1all[(m0 + mm) * H + kc + k];
        }
        for (int i = tid; i < 64 * 32; i += 256) {
            int nn = i >> 5, k = i & 31;
            Bs[k][nn] = fcW[(size_t)nn * H + kc + k];
        }
        __syncthreads();
#pragma unroll
        for (int k = 0; k < 32; k++) {
            float a[8], bb[4];
#pragma unroll
            for (int i = 0; i < 8; i++) a[i] = As[k][ty * 8 + i];
#pragma unroll
            for (int j = 0; j < 4; j++) bb[j] = Bs[k][tx * 4 + j];
#pragma unroll
            for (int i = 0; i < 8; i++)
#pragma unroll
                for (int j = 0; j < 4; j++) acc[i][j] += a[i] * bb[j];
        }
        __syncthreads();
    }
#pragma unroll
    for (int i = 0; i < 8; i++) {
        size_t row = (m0 + ty * 8 + i) * OUTN + tx * 4;
#pragma unroll
        for (int j = 0; j < 4; j++)
            g_logits[row + j] = acc[i][j] + fcb[tx * 4 + j];
    }
}

// ---------------- softmax over 64, remap [t][b] -> out[b][t] -----------------------
__global__ void softmax_kernel(float* __restrict__ out) {
    const int tid = threadIdx.x;
    const int lane = tid & 31, w = tid >> 5;
    size_t row = (size_t)blockIdx.x * 8 + w;
    const float* L = g_logits + row * OUTN;
    float v0 = L[lane], v1 = L[lane + 32];
    float mx = fmaxf(v0, v1);
#pragma unroll
    for (int off = 16; off; off >>= 1) mx = fmaxf(mx, __shfl_xor_sync(~0u, mx, off));
    float e0 = expf(v0 - mx), e1 = expf(v1 - mx);
    float s = e0 + e1;
#pragma unroll
    for (int off = 16; off; off >>= 1) s += __shfl_xor_sync(~0u, s, off);
    float inv = 1.f / s;
    int t = (int)(row >> 6), b = (int)(row & 63);
    float* O = out + ((size_t)b * T + t) * OUTN;
    O[lane]      = e0 * inv;
    O[lane + 32] = e1 * inv;
}

// ---------------- launch -------------------------------------------------------------
extern "C" void kernel_launch(void* const* d_in, const int* in_sizes, int n_in,
                              void* d_out, int out_size) {
    const int*   x     = (const int*)d_in[0];
    const float* table = (const float*)d_in[1];
    const float* Wih0  = (const float*)d_in[2];
    const float* Whh0  = (const float*)d_in[3];
    const float* bih0  = (const float*)d_in[4];
    const float* bhh0  = (const float*)d_in[5];
    const float* Wih1  = (const float*)d_in[6];
    const float* Whh1  = (const float*)d_in[7];
    const float* bih1  = (const float*)d_in[8];
    const float* bhh1  = (const float*)d_in[9];
    const float* fcW   = (const float*)d_in[10];
    const float* fcb   = (const float*)d_in[11];
    float* out = (float*)d_out;

    cudaFuncSetAttribute(lstm_kernel,
                         cudaFuncAttributeMaxDynamicSharedMemorySize, SMEM_BYTES);

    void *p0, *p1, *ph0, *ph1;
    cudaGetSymbolAddress(&p0,  g_done0q);
    cudaGetSymbolAddress(&p1,  g_done1q);
    cudaGetSymbolAddress(&ph0, g_h0buf);
    cudaGetSymbolAddress(&ph1, g_h1buf);
    cudaMemsetAsync(p0,  0, T * 4 * sizeof(int));
    cudaMemsetAsync(p1,  0, T * 4 * sizeof(int));
    cudaMemsetAsync(ph0, 0, RING * B * H * sizeof(__half));
    cudaMemsetAsync(ph1, 0, RING * B * H * sizeof(__half));

    prep_bias<<<4, 256>>>(bih0, bhh0, bih1, bhh1);
    embed_kernel<<<(MROWS * D) / 256, 256>>>(x, table);
    gemm_xg0<<<dim3(8, MROWS / 128), 256>>>(Wih0);

    lstm_kernel<<<NBLK, 256, SMEM_BYTES>>>(Whh0, Wih1, Whh1);

    gemm_fc<<<MROWS / 128, 256>>>(fcW, fcb);
    softmax_kernel<<<MROWS / 8, 256>>>(out);
}